// round 2
// baseline (speedup 1.0000x reference)
#include <cuda_runtime.h>
#include <math.h>
#include <stdint.h>

// ---------------- problem constants ----------------
#define BATCH   256
#define SEQ     4
#define MROWS   (BATCH*SEQ)      // 1024
#define HID     2048
#define EMBED_IN 3072
#define NCLASS  1000
#define ATTN_SCALE 0.022097086912079608f   // 1/sqrt(2048)

// ---------------- scratch (device globals; no allocs allowed) ----------------
__device__ float g_t  [MROWS * EMBED_IN];   // patchified+masked input
__device__ float g_h  [MROWS * HID];        // residual stream
__device__ float g_y  [MROWS * HID];        // layernorm output
__device__ float g_z  [MROWS * HID * 2];    // mlp mid (4096)
__device__ float g_qkv[MROWS * HID * 3];    // qkv (6144)
__device__ float g_o  [MROWS * HID];        // attention output
__device__ float g_f1 [BATCH * HID];
__device__ float g_f2 [BATCH * HID];

// ---------------- patchify + mask -> t (1024 x 3072) ----------------
// t[row=b*4+s][e = q*48 + d], n = s*64+q, d = c*16 + i*4 + j
// value = x[b][c][pr*4+i][pc*4+j] * mask[b][n][d]
__global__ void patchify_kernel(const float* __restrict__ x,
                                const float* __restrict__ mask) {
    int idx = blockIdx.x * 256 + threadIdx.x;
    if (idx >= MROWS * EMBED_IN) return;
    int row = idx / EMBED_IN;
    int e   = idx - row * EMBED_IN;
    int q   = e / 48;
    int d   = e - q * 48;
    int b   = row >> 2;
    int s   = row & 3;
    int n   = s * 64 + q;
    int pr  = n >> 4, pc = n & 15;
    int c   = d >> 4;
    int r   = d & 15;
    int i   = r >> 2, j = r & 3;
    float xv = x[((size_t)(b * 3 + c) * 64 + (pr * 4 + i)) * 64 + (pc * 4 + j)];
    float mv = mask[((size_t)b * 256 + n) * 48 + d];
    g_t[idx] = xv * mv;
}

// ---------------- layernorm (one block per row of 2048) ----------------
__global__ void ln_kernel(const float* __restrict__ h,
                          const float* __restrict__ gw,
                          const float* __restrict__ bw,
                          float* __restrict__ y) {
    int row = blockIdx.x;
    const float* xr = h + (size_t)row * HID;
    float s = 0.f, sq = 0.f;
    for (int c = threadIdx.x; c < HID; c += 256) {
        float v = xr[c];
        s += v;
        sq = fmaf(v, v, sq);
    }
    #pragma unroll
    for (int o = 16; o; o >>= 1) {
        s  += __shfl_xor_sync(0xffffffffu, s, o);
        sq += __shfl_xor_sync(0xffffffffu, sq, o);
    }
    __shared__ float ss[8], ssq[8];
    int w = threadIdx.x >> 5, l = threadIdx.x & 31;
    if (l == 0) { ss[w] = s; ssq[w] = sq; }
    __syncthreads();
    if (threadIdx.x == 0) {
        float a = 0.f, b2 = 0.f;
        #pragma unroll
        for (int i = 0; i < 8; i++) { a += ss[i]; b2 += ssq[i]; }
        ss[0] = a; ssq[0] = b2;
    }
    __syncthreads();
    float mean = ss[0] * (1.f / HID);
    float var  = ssq[0] * (1.f / HID) - mean * mean;   // biased var, like jnp.var
    float inv  = rsqrtf(var + 1e-5f);
    for (int c = threadIdx.x; c < HID; c += 256)
        y[(size_t)row * HID + c] = (xr[c] - mean) * inv * gw[c] + bw[c];
}

// ---------------- attention: per (batch, head); seq=4, dh=512 ----------------
__global__ void attn_kernel(const float* __restrict__ qkv, float* __restrict__ o) {
    int b  = blockIdx.x >> 2;
    int hd = blockIdx.x & 3;
    const float* base = qkv + (size_t)b * 4 * 6144 + hd * 512;   // q at +0, k at +2048, v at +4096
    int tid = threadIdx.x;   // 128 threads

    float p[16];
    #pragma unroll
    for (int ij = 0; ij < 16; ij++) p[ij] = 0.f;
    for (int d = tid; d < 512; d += 128) {
        float qv[4], kv[4];
        #pragma unroll
        for (int s = 0; s < 4; s++) {
            qv[s] = base[s * 6144 + d];
            kv[s] = base[s * 6144 + 2048 + d];
        }
        #pragma unroll
        for (int i = 0; i < 4; i++)
            #pragma unroll
            for (int j = 0; j < 4; j++)
                p[i * 4 + j] = fmaf(qv[i], kv[j], p[i * 4 + j]);
    }
    #pragma unroll
    for (int ij = 0; ij < 16; ij++)
        #pragma unroll
        for (int off = 16; off; off >>= 1)
            p[ij] += __shfl_xor_sync(0xffffffffu, p[ij], off);

    __shared__ float dsh[4][16];
    __shared__ float probs[16];
    int w = tid >> 5, l = tid & 31;
    if (l == 0) {
        #pragma unroll
        for (int ij = 0; ij < 16; ij++) dsh[w][ij] = p[ij];
    }
    __syncthreads();
    if (tid < 4) {   // row i = tid
        float row[4];
        #pragma unroll
        for (int j = 0; j < 4; j++)
            row[j] = (dsh[0][tid*4+j] + dsh[1][tid*4+j] + dsh[2][tid*4+j] + dsh[3][tid*4+j]) * ATTN_SCALE;
        float mx = fmaxf(fmaxf(row[0], row[1]), fmaxf(row[2], row[3]));
        float sum = 0.f;
        #pragma unroll
        for (int j = 0; j < 4; j++) { row[j] = expf(row[j] - mx); sum += row[j]; }
        float inv = 1.f / sum;
        #pragma unroll
        for (int j = 0; j < 4; j++) probs[tid * 4 + j] = row[j] * inv;
    }
    __syncthreads();
    for (int idx = tid; idx < 2048; idx += 128) {
        int i = idx >> 9, d = idx & 511;
        float acc = 0.f;
        #pragma unroll
        for (int j = 0; j < 4; j++)
            acc = fmaf(probs[i * 4 + j], base[j * 6144 + 4096 + d], acc);
        o[(size_t)(b * 4 + i) * 2048 + hd * 512 + d] = acc;
    }
}

// ---------------- fp32 tiled GEMM: C = epilogue(A(MxK) @ B(KxN) + bias) ----------------
// EPI: 0=none, 1=gelu(exact), 2=Cin + v (residual), 3=2*Cin + v, 4=leaky(0.2)
template<int EPI>
__global__ void __launch_bounds__(256)
sgemm(const float* __restrict__ A, const float* __restrict__ Bw,
      const float* __restrict__ bias, const float* __restrict__ Cin,
      float* __restrict__ Cout, int M, int N, int K) {
    __shared__ float As[16][64];   // [k][m] transposed
    __shared__ float Bs[16][64];   // [k][n]
    int tid  = threadIdx.x;
    int tx   = tid & 15, ty = tid >> 4;
    int row0 = blockIdx.y << 6;
    int col0 = blockIdx.x << 6;
    int ar   = tid >> 2, ak4 = (tid & 3) << 2;   // A: thread loads float4 along K
    int br   = tid >> 4, bn4 = (tid & 15) << 2;  // B: thread loads float4 along N
    float acc[4][4] = {};

    for (int k0 = 0; k0 < K; k0 += 16) {
        float4 av = *reinterpret_cast<const float4*>(&A[(size_t)(row0 + ar) * K + k0 + ak4]);
        As[ak4 + 0][ar] = av.x; As[ak4 + 1][ar] = av.y;
        As[ak4 + 2][ar] = av.z; As[ak4 + 3][ar] = av.w;
        float4 bv;
        if (col0 + bn4 < N)
            bv = *reinterpret_cast<const float4*>(&Bw[(size_t)(k0 + br) * N + col0 + bn4]);
        else
            bv = make_float4(0.f, 0.f, 0.f, 0.f);
        *reinterpret_cast<float4*>(&Bs[br][bn4]) = bv;
        __syncthreads();
        #pragma unroll
        for (int kk = 0; kk < 16; kk++) {
            float4 a4 = *reinterpret_cast<const float4*>(&As[kk][ty << 2]);
            float4 b4 = *reinterpret_cast<const float4*>(&Bs[kk][tx << 2]);
            float a[4] = {a4.x, a4.y, a4.z, a4.w};
            float b[4] = {b4.x, b4.y, b4.z, b4.w};
            #pragma unroll
            for (int i = 0; i < 4; i++)
                #pragma unroll
                for (int j = 0; j < 4; j++)
                    acc[i][j] = fmaf(a[i], b[j], acc[i][j]);
        }
        __syncthreads();
    }
    #pragma unroll
    for (int i = 0; i < 4; i++) {
        int r = row0 + (ty << 2) + i;
        #pragma unroll
        for (int j = 0; j < 4; j++) {
            int c = col0 + (tx << 2) + j;
            if (c >= N) continue;
            float v = acc[i][j] + bias[c];
            if (EPI == 1)      v = 0.5f * v * (1.f + erff(v * 0.7071067811865475f));
            else if (EPI == 2) v = v + Cin[(size_t)r * N + c];
            else if (EPI == 3) v = v + 2.f * Cin[(size_t)r * N + c];
            else if (EPI == 4) v = (v > 0.f) ? v : 0.2f * v;
            Cout[(size_t)r * N + c] = v;
        }
    }
}

// ---------------- host orchestration ----------------
extern "C" void kernel_launch(void* const* d_in, const int* in_sizes, int n_in,
                              void* d_out, int out_size) {
    const float* x       = (const float*)d_in[0];
    const float* mask    = (const float*)d_in[1];
    const float* embed_w = (const float*)d_in[2];
    const float* embed_b = (const float*)d_in[3];
    const float* ln_g    = (const float*)d_in[4];
    const float* ln_b    = (const float*)d_in[5];
    const float* mlp_w1  = (const float*)d_in[6];
    const float* mlp_b1  = (const float*)d_in[7];
    const float* mlp_w2  = (const float*)d_in[8];
    const float* mlp_b2  = (const float*)d_in[9];
    const float* qkv_w   = (const float*)d_in[10];
    const float* qkv_b   = (const float*)d_in[11];
    const float* out_w   = (const float*)d_in[12];
    const float* out_b   = (const float*)d_in[13];
    const float* fc1_w   = (const float*)d_in[14];
    const float* fc1_b   = (const float*)d_in[15];
    const float* fc2_w   = (const float*)d_in[16];
    const float* fc2_b   = (const float*)d_in[17];
    const float* fc3_w   = (const float*)d_in[18];
    const float* fc3_b   = (const float*)d_in[19];
    float* out = (float*)d_out;

    float *t, *h, *y, *z, *qkv, *o, *f1, *f2;
    cudaGetSymbolAddress((void**)&t,   g_t);
    cudaGetSymbolAddress((void**)&h,   g_h);
    cudaGetSymbolAddress((void**)&y,   g_y);
    cudaGetSymbolAddress((void**)&z,   g_z);
    cudaGetSymbolAddress((void**)&qkv, g_qkv);
    cudaGetSymbolAddress((void**)&o,   g_o);
    cudaGetSymbolAddress((void**)&f1,  g_f1);
    cudaGetSymbolAddress((void**)&f2,  g_f2);

    // 1) patchify + mask
    patchify_kernel<<<(MROWS * EMBED_IN + 255) / 256, 256>>>(x, mask);

    // 2) embed: (1024,3072)@(3072,2048)
    sgemm<0><<<dim3(HID / 64, MROWS / 64), 256>>>(t, embed_w, embed_b, nullptr, h,
                                                  MROWS, HID, EMBED_IN);

    // 3) 4 MLP blocks
    for (int i = 0; i < 4; i++) {
        ln_kernel<<<MROWS, 256>>>(h, ln_g + (size_t)i * HID, ln_b + (size_t)i * HID, y);
        sgemm<1><<<dim3(2 * HID / 64, MROWS / 64), 256>>>(
            y, mlp_w1 + (size_t)i * HID * 2 * HID, mlp_b1 + (size_t)i * 2 * HID,
            nullptr, z, MROWS, 2 * HID, HID);
        sgemm<2><<<dim3(HID / 64, MROWS / 64), 256>>>(
            z, mlp_w2 + (size_t)i * 2 * HID * HID, mlp_b2 + (size_t)i * HID,
            h, h, MROWS, HID, 2 * HID);
    }

    // 4) 4 attention blocks (h_new = 2h + o@out_w + out_b)
    for (int i = 0; i < 4; i++) {
        sgemm<0><<<dim3(3 * HID / 64, MROWS / 64), 256>>>(
            h, qkv_w + (size_t)i * HID * 3 * HID, qkv_b + (size_t)i * 3 * HID,
            nullptr, qkv, MROWS, 3 * HID, HID);
        attn_kernel<<<BATCH * 4, 128>>>(qkv, o);
        sgemm<3><<<dim3(HID / 64, MROWS / 64), 256>>>(
            o, out_w + (size_t)i * HID * HID, out_b + (size_t)i * HID,
            h, h, MROWS, HID, HID);
    }

    // 5) final FCs; f = h viewed as (256, 8192) (contiguous reshape)
    sgemm<4><<<dim3(HID / 64, BATCH / 64), 256>>>(h,  fc1_w, fc1_b, nullptr, f1,
                                                  BATCH, HID, SEQ * HID);
    sgemm<4><<<dim3(HID / 64, BATCH / 64), 256>>>(f1, fc2_w, fc2_b, nullptr, f2,
                                                  BATCH, HID, HID);
    sgemm<0><<<dim3((NCLASS + 63) / 64, BATCH / 64), 256>>>(f2, fc3_w, fc3_b, nullptr, out,
                                                            BATCH, NCLASS, HID);
}

// round 9
// speedup vs baseline: 2.0775x; 2.0775x over previous
#include <cuda_runtime.h>
#include <cuda_bf16.h>
#include <math.h>
#include <stdint.h>

// ---------------- problem constants ----------------
#define BATCH   256
#define SEQ     4
#define MROWS   (BATCH*SEQ)      // 1024
#define HID     2048
#define EMBED_IN 3072
#define NCLASS  1000
#define ATTN_SCALE 0.022097086912079608f   // 1/sqrt(2048)

// ---------------- scratch (device globals; no allocs allowed) ----------------
__device__ float g_t  [MROWS * EMBED_IN];
__device__ float g_h  [MROWS * HID];
__device__ float g_y  [MROWS * HID];
__device__ float g_z  [MROWS * HID * 2];
__device__ float g_qkv[MROWS * HID * 3];
__device__ float g_o  [MROWS * HID];
__device__ float g_f1 [BATCH * HID];
__device__ float g_f2 [BATCH * HID];

// bf16 hi/lo transposed weights: layout per matrix = [hi: N*K][lo: N*K], batched blocks consecutive
__device__ __nv_bfloat16 g_embw[2 * 2048 * 3072];
__device__ __nv_bfloat16 g_m1w [4 * 2 * 4096 * 2048];
__device__ __nv_bfloat16 g_m2w [4 * 2 * 2048 * 4096];
__device__ __nv_bfloat16 g_qkvw[4 * 2 * 6144 * 2048];
__device__ __nv_bfloat16 g_outw[4 * 2 * 2048 * 2048];
__device__ __nv_bfloat16 g_f1w [2 * 2048 * 8192];
__device__ __nv_bfloat16 g_f2w [2 * 2048 * 2048];
__device__ __nv_bfloat16 g_f3w [2 * 1024 * 2048];

// ---------------- PTX helpers ----------------
__device__ __forceinline__ uint32_t smem_u32(const void* p) {
    uint32_t a;
    asm("{ .reg .u64 t; cvta.to.shared.u64 t, %1; cvt.u32.u64 %0, t; }" : "=r"(a) : "l"(p));
    return a;
}

#if defined(__CUDA_ARCH__) && defined(__CUDA_ARCH_FEAT_SM103_ALL)
#define HAVE_TCGEN05 1
#else
#define HAVE_TCGEN05 0
#endif

#if HAVE_TCGEN05
__device__ __forceinline__ uint32_t elect_one() {
    uint32_t pred;
    asm volatile("{\n\t.reg .pred p;\n\telect.sync _|p, 0xFFFFFFFF;\n\tselp.b32 %0, 1, 0, p;\n\t}" : "=r"(pred));
    return pred;
}
#define TC_ALLOC(sa, n)   asm volatile("tcgen05.alloc.cta_group::1.sync.aligned.shared::cta.b32 [%0], %1;" :: "r"((uint32_t)(sa)), "r"((uint32_t)(n)) : "memory")
#define TC_DEALLOC(t, n)  asm volatile("tcgen05.dealloc.cta_group::1.sync.aligned.b32 %0, %1;" :: "r"(t), "r"((uint32_t)(n)))
#define TC_RELINQ()       asm volatile("tcgen05.relinquish_alloc_permit.cta_group::1.sync.aligned;")
#define TC_COMMIT(mb)     asm volatile("tcgen05.commit.cta_group::1.mbarrier::arrive::one.shared::cluster.b64 [%0];" :: "r"((uint32_t)(mb)) : "memory")
#define TC_FENCE_AFTER()  asm volatile("tcgen05.fence::after_thread_sync;" ::: "memory")
#define TC_FENCE_BEFORE() asm volatile("tcgen05.fence::before_thread_sync;" ::: "memory")
#define TC_WAIT_LD()      asm volatile("tcgen05.wait::ld.sync.aligned;" ::: "memory")
#define FENCE_ASYNC()     asm volatile("fence.proxy.async.shared::cta;" ::: "memory")
#define MBAR_INIT(mb, c)  asm volatile("mbarrier.init.shared.b64 [%0], %1;" :: "r"((uint32_t)(mb)), "r"((uint32_t)(c)) : "memory")
#define MBAR_INVAL(mb)    asm volatile("mbarrier.inval.shared.b64 [%0];" :: "r"((uint32_t)(mb)) : "memory")

// BOUNDED wait: converts any lost-arrival bug from a container-killing hang
// into a finite run with wrong output (diagnosable rel_err + profile).
#define MBAR_WAIT(mb, ph) do {                                                    \
    uint32_t _mb = (uint32_t)(mb); uint32_t _p = (uint32_t)(ph); uint32_t _d = 0; \
    for (int _i = 0; _i < (1 << 24); _i++) {                                      \
        asm volatile("{\n\t.reg .pred p;\n\t"                                     \
            "mbarrier.try_wait.parity.acquire.cta.shared::cta.b64 p, [%1], %2;\n\t" \
            "selp.b32 %0, 1, 0, p;\n\t}" : "=r"(_d) : "r"(_mb), "r"(_p) : "memory"); \
        if (_d) break;                                                            \
    }                                                                             \
} while (0)

#define TC_LD_X32(r, ta)                                                          \
    asm volatile("tcgen05.ld.sync.aligned.32x32b.x32.b32 "                        \
        "{%0,%1,%2,%3,%4,%5,%6,%7,%8,%9,%10,%11,%12,%13,%14,%15,"                 \
        "%16,%17,%18,%19,%20,%21,%22,%23,%24,%25,%26,%27,%28,%29,%30,%31}, [%32];"\
        : "=r"((r)[0]),"=r"((r)[1]),"=r"((r)[2]),"=r"((r)[3]),                    \
          "=r"((r)[4]),"=r"((r)[5]),"=r"((r)[6]),"=r"((r)[7]),                    \
          "=r"((r)[8]),"=r"((r)[9]),"=r"((r)[10]),"=r"((r)[11]),                  \
          "=r"((r)[12]),"=r"((r)[13]),"=r"((r)[14]),"=r"((r)[15]),                \
          "=r"((r)[16]),"=r"((r)[17]),"=r"((r)[18]),"=r"((r)[19]),                \
          "=r"((r)[20]),"=r"((r)[21]),"=r"((r)[22]),"=r"((r)[23]),                \
          "=r"((r)[24]),"=r"((r)[25]),"=r"((r)[26]),"=r"((r)[27]),                \
          "=r"((r)[28]),"=r"((r)[29]),"=r"((r)[30]),"=r"((r)[31])                 \
        : "r"(ta))

__device__ __forceinline__ void mma_ss_f16(uint32_t d, uint64_t ad, uint64_t bd,
                                           uint32_t idesc, uint32_t en) {
    asm volatile(
        "{\n\t.reg .pred p;\n\tsetp.ne.u32 p, %4, 0;\n\t"
        "tcgen05.mma.cta_group::1.kind::f16 [%0], %1, %2, %3, {%5,%5,%5,%5}, p;\n\t}"
        :: "r"(d), "l"(ad), "l"(bd), "r"(idesc), "r"(en), "r"(0u) : "memory");
}
#endif  // HAVE_TCGEN05

static constexpr uint64_t DESC_BASE_SW128 =
    (uint64_t(2) << 61) | (uint64_t(1) << 46) | (uint64_t(64) << 32) | (uint64_t(1) << 16);
#define MK_DESC(a) (DESC_BASE_SW128 | ((uint64_t)((a) >> 4) & 0x3FFF))
#define SWZ128(o)  ((o) ^ (((o) >> 3) & 0x70))

// ---------------- patchify + mask ----------------
__global__ void patchify_kernel(const float* __restrict__ x,
                                const float* __restrict__ mask) {
    int idx = blockIdx.x * 256 + threadIdx.x;
    if (idx >= MROWS * EMBED_IN) return;
    int row = idx / EMBED_IN;
    int e   = idx - row * EMBED_IN;
    int q   = e / 48;
    int d   = e - q * 48;
    int b   = row >> 2;
    int s   = row & 3;
    int n   = s * 64 + q;
    int pr  = n >> 4, pc = n & 15;
    int c   = d >> 4;
    int r   = d & 15;
    int i   = r >> 2, j = r & 3;
    float xv = x[((size_t)(b * 3 + c) * 64 + (pr * 4 + i)) * 64 + (pc * 4 + j)];
    float mv = mask[((size_t)b * 256 + n) * 48 + d];
    g_t[idx] = xv * mv;
}

// ---------------- weight transpose + bf16 hi/lo split ----------------
__global__ void convT_kernel(const float* __restrict__ W, __nv_bfloat16* __restrict__ dst,
                             int K, int Npad, int Nsrc,
                             size_t srcStride, size_t dstStride) {
    int z = blockIdx.z;
    const float* src = W + (size_t)z * srcStride;
    __nv_bfloat16* hi = dst + (size_t)z * dstStride;
    __nv_bfloat16* lo = hi + (size_t)Npad * K;
    __shared__ float t[32][33];
    int k0 = blockIdx.y * 32, n0 = blockIdx.x * 32;
    for (int i = threadIdx.y; i < 32; i += 8) {
        int n = n0 + threadIdx.x;
        t[i][threadIdx.x] = (n < Nsrc) ? src[(size_t)(k0 + i) * Nsrc + n] : 0.f;
    }
    __syncthreads();
    for (int i = threadIdx.y; i < 32; i += 8) {
        int n = n0 + i, k = k0 + threadIdx.x;
        float v = t[threadIdx.x][i];
        __nv_bfloat16 h = __float2bfloat16(v);
        float r = v - __bfloat162float(h);
        hi[(size_t)n * K + k] = h;
        lo[(size_t)n * K + k] = __float2bfloat16(r);
    }
}

// ---------------- layernorm ----------------
__global__ void ln_kernel(const float* __restrict__ h,
                          const float* __restrict__ gw,
                          const float* __restrict__ bw,
                          float* __restrict__ y) {
    int row = blockIdx.x;
    const float* xr = h + (size_t)row * HID;
    float s = 0.f, sq = 0.f;
    for (int c = threadIdx.x; c < HID; c += 256) {
        float v = xr[c];
        s += v;
        sq = fmaf(v, v, sq);
    }
    #pragma unroll
    for (int o = 16; o; o >>= 1) {
        s  += __shfl_xor_sync(0xffffffffu, s, o);
        sq += __shfl_xor_sync(0xffffffffu, sq, o);
    }
    __shared__ float ss[8], ssq[8];
    int w = threadIdx.x >> 5, l = threadIdx.x & 31;
    if (l == 0) { ss[w] = s; ssq[w] = sq; }
    __syncthreads();
    if (threadIdx.x == 0) {
        float a = 0.f, b2 = 0.f;
        #pragma unroll
        for (int i = 0; i < 8; i++) { a += ss[i]; b2 += ssq[i]; }
        ss[0] = a; ssq[0] = b2;
    }
    __syncthreads();
    float mean = ss[0] * (1.f / HID);
    float var  = ssq[0] * (1.f / HID) - mean * mean;
    float inv  = rsqrtf(var + 1e-5f);
    for (int c = threadIdx.x; c < HID; c += 256)
        y[(size_t)row * HID + c] = (xr[c] - mean) * inv * gw[c] + bw[c];
}

// ---------------- attention: per (batch, head); seq=4, dh=512 ----------------
__global__ void attn_kernel(const float* __restrict__ qkv, float* __restrict__ o) {
    int b  = blockIdx.x >> 2;
    int hd = blockIdx.x & 3;
    const float* base = qkv + (size_t)b * 4 * 6144 + hd * 512;
    int tid = threadIdx.x;

    float p[16];
    #pragma unroll
    for (int ij = 0; ij < 16; ij++) p[ij] = 0.f;
    for (int d = tid; d < 512; d += 128) {
        float qv[4], kv[4];
        #pragma unroll
        for (int s = 0; s < 4; s++) {
            qv[s] = base[s * 6144 + d];
            kv[s] = base[s * 6144 + 2048 + d];
        }
        #pragma unroll
        for (int i = 0; i < 4; i++)
            #pragma unroll
            for (int j = 0; j < 4; j++)
                p[i * 4 + j] = fmaf(qv[i], kv[j], p[i * 4 + j]);
    }
    #pragma unroll
    for (int ij = 0; ij < 16; ij++)
        #pragma unroll
        for (int off = 16; off; off >>= 1)
            p[ij] += __shfl_xor_sync(0xffffffffu, p[ij], off);

    __shared__ float dsh[4][16];
    __shared__ float probs[16];
    int w = tid >> 5, l = tid & 31;
    if (l == 0) {
        #pragma unroll
        for (int ij = 0; ij < 16; ij++) dsh[w][ij] = p[ij];
    }
    __syncthreads();
    if (tid < 4) {
        float row[4];
        #pragma unroll
        for (int j = 0; j < 4; j++)
            row[j] = (dsh[0][tid*4+j] + dsh[1][tid*4+j] + dsh[2][tid*4+j] + dsh[3][tid*4+j]) * ATTN_SCALE;
        float mx = fmaxf(fmaxf(row[0], row[1]), fmaxf(row[2], row[3]));
        float sum = 0.f;
        #pragma unroll
        for (int j = 0; j < 4; j++) { row[j] = expf(row[j] - mx); sum += row[j]; }
        float inv = 1.f / sum;
        #pragma unroll
        for (int j = 0; j < 4; j++) probs[tid * 4 + j] = row[j] * inv;
    }
    __syncthreads();
    for (int idx = tid; idx < 2048; idx += 128) {
        int i = idx >> 9, d = idx & 511;
        float acc = 0.f;
        #pragma unroll
        for (int j = 0; j < 4; j++)
            acc = fmaf(probs[i * 4 + j], base[j * 6144 + 4096 + d], acc);
        o[(size_t)(b * 4 + i) * 2048 + hd * 512 + d] = acc;
    }
}

// ---------------- bf16-split GEMM: tcgen05 on sm_103a, FFMA fallback otherwise ----
// C[M,N] = EPI(A[M,K]fp32 @ W[K,N] + bias); W pre-split to bf16 hi/lo [Npad,K]
// EPI: 0=none, 1=gelu(exact), 2=Cin+v, 3=2*Cin+v, 4=leaky(0.2)
#define TG_BM 128
#define TG_BN 128
#define TG_BK 64
#define TG_SMEM 66560
#define TG_IDESC ((1u<<4)|(1u<<7)|(1u<<10)|((TG_BN/8)<<17)|((TG_BM/16)<<24))

template<int EPI>
__device__ __forceinline__ float apply_epi(float v, const float* __restrict__ Cin,
                                           int row, int col, int Nout) {
    if (EPI == 1)      v = 0.5f * v * (1.f + erff(v * 0.7071067811865475f));
    else if (EPI == 2) v = v + Cin[(size_t)row * Nout + col];
    else if (EPI == 3) v = v + 2.f * Cin[(size_t)row * Nout + col];
    else if (EPI == 4) v = (v > 0.f) ? v : 0.2f * v;
    return v;
}

template<int EPI>
__global__ void __launch_bounds__(256, 1)
tgemm(const float* __restrict__ A, const __nv_bfloat16* __restrict__ Bhi,
      const float* __restrict__ bias, const float* __restrict__ Cin,
      float* __restrict__ Cout, int M, int Nout, int K, int Npad) {
    extern __shared__ char smem[];
    const __nv_bfloat16* Blo = Bhi + (size_t)Npad * K;
    int tid = threadIdx.x;
    int row0 = blockIdx.y * TG_BM;
    int col0 = blockIdx.x * TG_BN;

    const int SM_AH = 1024, SM_AL = SM_AH + 16384;
    const int SM_BH = SM_AL + 16384, SM_BL = SM_BH + 16384;

#if HAVE_TCGEN05
    uint32_t sb = smem_u32(smem);
    int wid = tid >> 5, lid = tid & 31;
    const int SM_TM = 0, SM_MB = 8;
    if (wid == 0) { TC_ALLOC(sb + SM_TM, 128); TC_RELINQ(); }
    if (tid == 0) MBAR_INIT(sb + SM_MB, 1);
    __syncthreads();
    uint32_t tb;
    asm volatile("ld.shared.b32 %0, [%1];" : "=r"(tb) : "r"(sb + SM_TM));

    uint64_t adh = MK_DESC(sb + SM_AH), adl = MK_DESC(sb + SM_AL);
    uint64_t bdh = MK_DESC(sb + SM_BH), bdl = MK_DESC(sb + SM_BL);

    int phase = 0;
    for (int k0 = 0; k0 < K; k0 += TG_BK) {
        #pragma unroll
        for (int it = 0; it < 8; it++) {
            int idx = it * 256 + tid;
            int r   = idx >> 4;
            int kq  = (idx & 15) << 2;
            float4 v = *reinterpret_cast<const float4*>(&A[(size_t)(row0 + r) * K + k0 + kq]);
            __nv_bfloat16 h0 = __float2bfloat16(v.x), h1 = __float2bfloat16(v.y);
            __nv_bfloat16 h2 = __float2bfloat16(v.z), h3 = __float2bfloat16(v.w);
            __nv_bfloat16 l0 = __float2bfloat16(v.x - __bfloat162float(h0));
            __nv_bfloat16 l1 = __float2bfloat16(v.y - __bfloat162float(h1));
            __nv_bfloat16 l2 = __float2bfloat16(v.z - __bfloat162float(h2));
            __nv_bfloat16 l3 = __float2bfloat16(v.w - __bfloat162float(h3));
            uint32_t off = SWZ128((uint32_t)(r * 128 + kq * 2));
            __nv_bfloat162 hp0; hp0.x = h0; hp0.y = h1;
            __nv_bfloat162 hp1; hp1.x = h2; hp1.y = h3;
            __nv_bfloat162 lp0; lp0.x = l0; lp0.y = l1;
            __nv_bfloat162 lp1; lp1.x = l2; lp1.y = l3;
            *reinterpret_cast<__nv_bfloat162*>(smem + SM_AH + off)     = hp0;
            *reinterpret_cast<__nv_bfloat162*>(smem + SM_AH + off + 4) = hp1;
            *reinterpret_cast<__nv_bfloat162*>(smem + SM_AL + off)     = lp0;
            *reinterpret_cast<__nv_bfloat162*>(smem + SM_AL + off + 4) = lp1;
        }
        #pragma unroll
        for (int it = 0; it < 4; it++) {
            int idx = it * 256 + tid;
            int r   = idx >> 3;
            int b16 = (idx & 7) << 4;
            const char* ph = (const char*)Bhi + ((size_t)(col0 + r) * K + k0) * 2 + b16;
            const char* pl = (const char*)Blo + ((size_t)(col0 + r) * K + k0) * 2 + b16;
            float4 vh = *reinterpret_cast<const float4*>(ph);
            float4 vl = *reinterpret_cast<const float4*>(pl);
            uint32_t off = SWZ128((uint32_t)(r * 128 + b16));
            *reinterpret_cast<float4*>(smem + SM_BH + off) = vh;
            *reinterpret_cast<float4*>(smem + SM_BL + off) = vl;
        }
        // make generic SMEM writes visible to the tcgen05 async proxy, then sync
        FENCE_ASYNC();
        TC_FENCE_BEFORE();
        __syncthreads();
        if (wid == 0 && elect_one()) {
            TC_FENCE_AFTER();
            #pragma unroll
            for (int t = 0; t < 3; t++) {
                uint64_t ad = (t == 2) ? adl : adh;
                uint64_t bd = (t == 1) ? bdl : bdh;
                #pragma unroll
                for (int s = 0; s < 4; s++) {
                    uint32_t en = (k0 > 0) || (t > 0) || (s > 0);
                    mma_ss_f16(tb, ad + s * 2, bd + s * 2, TG_IDESC, en);
                }
            }
            TC_COMMIT(sb + SM_MB);
        }
        MBAR_WAIT(sb + SM_MB, phase);
        phase ^= 1;
    }
    TC_FENCE_AFTER();

    // epilogue: warpgroup 0 (warps 0-3), each warp = its 32-row subpartition,
    // 4 chunks of 32 columns (example-faithful read pattern)
    if (wid < 4) {
        int row = row0 + wid * 32 + lid;
        #pragma unroll
        for (int ch = 0; ch < 4; ch++) {
            uint32_t r[32];
            TC_LD_X32(r, tb + ch * 32);
            TC_WAIT_LD();
            #pragma unroll
            for (int c = 0; c < 32; c++) {
                int col = col0 + ch * 32 + c;
                if (col >= Nout) continue;
                float v = __uint_as_float(r[c]) + bias[col];
                Cout[(size_t)row * Nout + col] = apply_epi<EPI>(v, Cin, row, col, Nout);
            }
        }
        TC_FENCE_BEFORE();
    }
    __syncthreads();
    if (tid == 0) MBAR_INVAL(sb + SM_MB);
    __syncthreads();
    if (wid == 0) TC_DEALLOC(tb, 128);

#else  // ---------------- FFMA fallback (compiled for non-103a targets) ----------------
    int ty = tid >> 4, tx = tid & 15;          // 16x16 threads, 8x8 outputs each
    float acc[8][8];
    #pragma unroll
    for (int i = 0; i < 8; i++)
        #pragma unroll
        for (int j = 0; j < 8; j++) acc[i][j] = 0.f;

    for (int k0 = 0; k0 < K; k0 += TG_BK) {
        #pragma unroll
        for (int it = 0; it < 8; it++) {
            int idx = it * 256 + tid;
            int r   = idx >> 4;
            int kq  = (idx & 15) << 2;
            float4 v = *reinterpret_cast<const float4*>(&A[(size_t)(row0 + r) * K + k0 + kq]);
            __nv_bfloat16 h0 = __float2bfloat16(v.x), h1 = __float2bfloat16(v.y);
            __nv_bfloat16 h2 = __float2bfloat16(v.z), h3 = __float2bfloat16(v.w);
            __nv_bfloat16 l0 = __float2bfloat16(v.x - __bfloat162float(h0));
            __nv_bfloat16 l1 = __float2bfloat16(v.y - __bfloat162float(h1));
            __nv_bfloat16 l2 = __float2bfloat16(v.z - __bfloat162float(h2));
            __nv_bfloat16 l3 = __float2bfloat16(v.w - __bfloat162float(h3));
            uint32_t off = SWZ128((uint32_t)(r * 128 + kq * 2));
            __nv_bfloat162 hp0; hp0.x = h0; hp0.y = h1;
            __nv_bfloat162 hp1; hp1.x = h2; hp1.y = h3;
            __nv_bfloat162 lp0; lp0.x = l0; lp0.y = l1;
            __nv_bfloat162 lp1; lp1.x = l2; lp1.y = l3;
            *reinterpret_cast<__nv_bfloat162*>(smem + SM_AH + off)     = hp0;
            *reinterpret_cast<__nv_bfloat162*>(smem + SM_AH + off + 4) = hp1;
            *reinterpret_cast<__nv_bfloat162*>(smem + SM_AL + off)     = lp0;
            *reinterpret_cast<__nv_bfloat162*>(smem + SM_AL + off + 4) = lp1;
        }
        #pragma unroll
        for (int it = 0; it < 4; it++) {
            int idx = it * 256 + tid;
            int r   = idx >> 3;
            int b16 = (idx & 7) << 4;
            const char* ph = (const char*)Bhi + ((size_t)(col0 + r) * K + k0) * 2 + b16;
            const char* pl = (const char*)Blo + ((size_t)(col0 + r) * K + k0) * 2 + b16;
            float4 vh = *reinterpret_cast<const float4*>(ph);
            float4 vl = *reinterpret_cast<const float4*>(pl);
            uint32_t off = SWZ128((uint32_t)(r * 128 + b16));
            *reinterpret_cast<float4*>(smem + SM_BH + off) = vh;
            *reinterpret_cast<float4*>(smem + SM_BL + off) = vl;
        }
        __syncthreads();
        #pragma unroll 4
        for (int kk = 0; kk < TG_BK; kk += 2) {
            float a0[8], a1[8], b0[8], b1[8];
            #pragma unroll
            for (int i = 0; i < 8; i++) {
                uint32_t off = SWZ128((uint32_t)((ty * 8 + i) * 128 + kk * 2));
                __nv_bfloat162 h = *reinterpret_cast<__nv_bfloat162*>(smem + SM_AH + off);
                __nv_bfloat162 l = *reinterpret_cast<__nv_bfloat162*>(smem + SM_AL + off);
                a0[i] = __bfloat162float(h.x) + __bfloat162float(l.x);
                a1[i] = __bfloat162float(h.y) + __bfloat162float(l.y);
            }
            #pragma unroll
            for (int j = 0; j < 8; j++) {
                uint32_t off = SWZ128((uint32_t)((tx * 8 + j) * 128 + kk * 2));
                __nv_bfloat162 h = *reinterpret_cast<__nv_bfloat162*>(smem + SM_BH + off);
                __nv_bfloat162 l = *reinterpret_cast<__nv_bfloat162*>(smem + SM_BL + off);
                b0[j] = __bfloat162float(h.x) + __bfloat162float(l.x);
                b1[j] = __bfloat162float(h.y) + __bfloat162float(l.y);
            }
            #pragma unroll
            for (int i = 0; i < 8; i++)
                #pragma unroll
                for (int j = 0; j < 8; j++) {
                    acc[i][j] = fmaf(a0[i], b0[j], acc[i][j]);
                    acc[i][j] = fmaf(a1[i], b1[j], acc[i][j]);
                }
        }
        __syncthreads();
    }
    #pragma unroll
    for (int i = 0; i < 8; i++) {
        int row = row0 + ty * 8 + i;
        #pragma unroll
        for (int j = 0; j < 8; j++) {
            int col = col0 + tx * 8 + j;
            if (col >= Nout) continue;
            float v = acc[i][j] + bias[col];
            Cout[(size_t)row * Nout + col] = apply_epi<EPI>(v, Cin, row, col, Nout);
        }
    }
#endif
}

// ---------------- host orchestration ----------------
extern "C" void kernel_launch(void* const* d_in, const int* in_sizes, int n_in,
                              void* d_out, int out_size) {
    const float* x       = (const float*)d_in[0];
    const float* mask    = (const float*)d_in[1];
    const float* embed_w = (const float*)d_in[2];
    const float* embed_b = (const float*)d_in[3];
    const float* ln_g    = (const float*)d_in[4];
    const float* ln_b    = (const float*)d_in[5];
    const float* mlp_w1  = (const float*)d_in[6];
    const float* mlp_b1  = (const float*)d_in[7];
    const float* mlp_w2  = (const float*)d_in[8];
    const float* mlp_b2  = (const float*)d_in[9];
    const float* qkv_w   = (const float*)d_in[10];
    const float* qkv_b   = (const float*)d_in[11];
    const float* out_w   = (const float*)d_in[12];
    const float* out_b   = (const float*)d_in[13];
    const float* fc1_w   = (const float*)d_in[14];
    const float* fc1_b   = (const float*)d_in[15];
    const float* fc2_w   = (const float*)d_in[16];
    const float* fc2_b   = (const float*)d_in[17];
    const float* fc3_w   = (const float*)d_in[18];
    const float* fc3_b   = (const float*)d_in[19];
    float* out = (float*)d_out;

    float *t, *h, *y, *z, *qkv, *o, *f1, *f2;
    cudaGetSymbolAddress((void**)&t,   g_t);
    cudaGetSymbolAddress((void**)&h,   g_h);
    cudaGetSymbolAddress((void**)&y,   g_y);
    cudaGetSymbolAddress((void**)&z,   g_z);
    cudaGetSymbolAddress((void**)&qkv, g_qkv);
    cudaGetSymbolAddress((void**)&o,   g_o);
    cudaGetSymbolAddress((void**)&f1,  g_f1);
    cudaGetSymbolAddress((void**)&f2,  g_f2);
    __nv_bfloat16 *wE, *wM1, *wM2, *wQ, *wO, *wF1, *wF2, *wF3;
    cudaGetSymbolAddress((void**)&wE,  g_embw);
    cudaGetSymbolAddress((void**)&wM1, g_m1w);
    cudaGetSymbolAddress((void**)&wM2, g_m2w);
    cudaGetSymbolAddress((void**)&wQ,  g_qkvw);
    cudaGetSymbolAddress((void**)&wO,  g_outw);
    cudaGetSymbolAddress((void**)&wF1, g_f1w);
    cudaGetSymbolAddress((void**)&wF2, g_f2w);
    cudaGetSymbolAddress((void**)&wF3, g_f3w);

    cudaFuncSetAttribute(tgemm<0>, cudaFuncAttributeMaxDynamicSharedMemorySize, TG_SMEM);
    cudaFuncSetAttribute(tgemm<1>, cudaFuncAttributeMaxDynamicSharedMemorySize, TG_SMEM);
    cudaFuncSetAttribute(tgemm<2>, cudaFuncAttributeMaxDynamicSharedMemorySize, TG_SMEM);
    cudaFuncSetAttribute(tgemm<3>, cudaFuncAttributeMaxDynamicSharedMemorySize, TG_SMEM);
    cudaFuncSetAttribute(tgemm<4>, cudaFuncAttributeMaxDynamicSharedMemorySize, TG_SMEM);

    dim3 cb(32, 8);
    convT_kernel<<<dim3(2048/32, 3072/32, 1), cb>>>(embed_w, wE, 3072, 2048, 2048, 0, 0);
    convT_kernel<<<dim3(4096/32, 2048/32, 4), cb>>>(mlp_w1, wM1, 2048, 4096, 4096,
                                                    (size_t)2048*4096, (size_t)2*4096*2048);
    convT_kernel<<<dim3(2048/32, 4096/32, 4), cb>>>(mlp_w2, wM2, 4096, 2048, 2048,
                                                    (size_t)4096*2048, (size_t)2*2048*4096);
    convT_kernel<<<dim3(6144/32, 2048/32, 4), cb>>>(qkv_w, wQ, 2048, 6144, 6144,
                                                    (size_t)2048*6144, (size_t)2*6144*2048);
    convT_kernel<<<dim3(2048/32, 2048/32, 4), cb>>>(out_w, wO, 2048, 2048, 2048,
                                                    (size_t)2048*2048, (size_t)2*2048*2048);
    convT_kernel<<<dim3(2048/32, 8192/32, 1), cb>>>(fc1_w, wF1, 8192, 2048, 2048, 0, 0);
    convT_kernel<<<dim3(2048/32, 2048/32, 1), cb>>>(fc2_w, wF2, 2048, 2048, 2048, 0, 0);
    convT_kernel<<<dim3(1024/32, 2048/32, 1), cb>>>(fc3_w, wF3, 2048, 1024, 1000, 0, 0);

    patchify_kernel<<<(MROWS * EMBED_IN + 255) / 256, 256>>>(x, mask);

    tgemm<0><<<dim3(HID/128, MROWS/128), 256, TG_SMEM>>>(t, wE, embed_b, nullptr, h,
                                                         MROWS, HID, EMBED_IN, HID);

    for (int i = 0; i < 4; i++) {
        ln_kernel<<<MROWS, 256>>>(h, ln_g + (size_t)i * HID, ln_b + (size_t)i * HID, y);
        tgemm<1><<<dim3(2*HID/128, MROWS/128), 256, TG_SMEM>>>(
            y, wM1 + (size_t)i * 2 * 4096 * 2048, mlp_b1 + (size_t)i * 2 * HID,
            nullptr, z, MROWS, 2 * HID, HID, 2 * HID);
        tgemm<2><<<dim3(HID/128, MROWS/128), 256, TG_SMEM>>>(
            z, wM2 + (size_t)i * 2 * 2048 * 4096, mlp_b2 + (size_t)i * HID,
            h, h, MROWS, HID, 2 * HID, HID);
    }

    for (int i = 0; i < 4; i++) {
        tgemm<0><<<dim3(3*HID/128, MROWS/128), 256, TG_SMEM>>>(
            h, wQ + (size_t)i * 2 * 6144 * 2048, qkv_b + (size_t)i * 3 * HID,
            nullptr, qkv, MROWS, 3 * HID, HID, 3 * HID);
        attn_kernel<<<BATCH * 4, 128>>>(qkv, o);
        tgemm<3><<<dim3(HID/128, MROWS/128), 256, TG_SMEM>>>(
            o, wO + (size_t)i * 2 * 2048 * 2048, out_b + (size_t)i * HID,
            h, h, MROWS, HID, HID, HID);
    }

    tgemm<4><<<dim3(HID/128, BATCH/128), 256, TG_SMEM>>>(h,  wF1, fc1_b, nullptr, f1,
                                                         BATCH, HID, SEQ * HID, HID);
    tgemm<4><<<dim3(HID/128, BATCH/128), 256, TG_SMEM>>>(f1, wF2, fc2_b, nullptr, f2,
                                                         BATCH, HID, HID, HID);
    tgemm<0><<<dim3(1024/128, BATCH/128), 256, TG_SMEM>>>(f2, wF3, fc3_b, nullptr, out,
                                                          BATCH, NCLASS, HID, 1024);
}

// round 10
// speedup vs baseline: 2.9302x; 1.4105x over previous
#include <cuda_runtime.h>
#include <cuda_bf16.h>
#include <math.h>
#include <stdint.h>

// ---------------- problem constants ----------------
#define BATCH   256
#define SEQ     4
#define MROWS   (BATCH*SEQ)      // 1024
#define HID     2048
#define EMBED_IN 3072
#define NCLASS  1000
#define ATTN_SCALE 0.022097086912079608f   // 1/sqrt(2048)

// ---------------- scratch (device globals; no allocs allowed) ----------------
__device__ float g_t  [MROWS * EMBED_IN];
__device__ float g_h  [MROWS * HID];
__device__ float g_y  [MROWS * HID];
__device__ float g_z  [MROWS * HID * 2];
__device__ float g_qkv[MROWS * HID * 3];
__device__ float g_o  [MROWS * HID];
__device__ float g_f1 [BATCH * HID];
__device__ float g_f2 [BATCH * HID];

// activation hi/lo bf16 staging (max 1024x4096 elements)
__device__ __nv_bfloat16 g_act[2 * 1024 * 4096];

// bf16 hi/lo transposed weights: layout per matrix = [hi: N*K][lo: N*K]
__device__ __nv_bfloat16 g_embw[2 * 2048 * 3072];
__device__ __nv_bfloat16 g_m1w [4 * 2 * 4096 * 2048];
__device__ __nv_bfloat16 g_m2w [4 * 2 * 2048 * 4096];
__device__ __nv_bfloat16 g_qkvw[4 * 2 * 6144 * 2048];
__device__ __nv_bfloat16 g_outw[4 * 2 * 2048 * 2048];
__device__ __nv_bfloat16 g_f1w [2 * 2048 * 8192];
__device__ __nv_bfloat16 g_f2w [2 * 2048 * 2048];
__device__ __nv_bfloat16 g_f3w [2 * 1024 * 2048];

// ---------------- PTX helpers ----------------
__device__ __forceinline__ uint32_t smem_u32(const void* p) {
    uint32_t a;
    asm("{ .reg .u64 t; cvta.to.shared.u64 t, %1; cvt.u32.u64 %0, t; }" : "=r"(a) : "l"(p));
    return a;
}

#if defined(__CUDA_ARCH__) && defined(__CUDA_ARCH_FEAT_SM103_ALL)
#define HAVE_TCGEN05 1
#else
#define HAVE_TCGEN05 0
#endif

#if HAVE_TCGEN05
__device__ __forceinline__ uint32_t elect_one() {
    uint32_t pred;
    asm volatile("{\n\t.reg .pred p;\n\telect.sync _|p, 0xFFFFFFFF;\n\tselp.b32 %0, 1, 0, p;\n\t}" : "=r"(pred));
    return pred;
}
#define TC_ALLOC(sa, n)   asm volatile("tcgen05.alloc.cta_group::1.sync.aligned.shared::cta.b32 [%0], %1;" :: "r"((uint32_t)(sa)), "r"((uint32_t)(n)) : "memory")
#define TC_DEALLOC(t, n)  asm volatile("tcgen05.dealloc.cta_group::1.sync.aligned.b32 %0, %1;" :: "r"(t), "r"((uint32_t)(n)))
#define TC_RELINQ()       asm volatile("tcgen05.relinquish_alloc_permit.cta_group::1.sync.aligned;")
#define TC_COMMIT(mb)     asm volatile("tcgen05.commit.cta_group::1.mbarrier::arrive::one.shared::cluster.b64 [%0];" :: "r"((uint32_t)(mb)) : "memory")
#define TC_FENCE_AFTER()  asm volatile("tcgen05.fence::after_thread_sync;" ::: "memory")
#define TC_FENCE_BEFORE() asm volatile("tcgen05.fence::before_thread_sync;" ::: "memory")
#define TC_WAIT_LD()      asm volatile("tcgen05.wait::ld.sync.aligned;" ::: "memory")
#define FENCE_ASYNC()     asm volatile("fence.proxy.async.shared::cta;" ::: "memory")
#define MBAR_INIT(mb, c)  asm volatile("mbarrier.init.shared.b64 [%0], %1;" :: "r"((uint32_t)(mb)), "r"((uint32_t)(c)) : "memory")
#define MBAR_INVAL(mb)    asm volatile("mbarrier.inval.shared.b64 [%0];" :: "r"((uint32_t)(mb)) : "memory")

// BOUNDED wait (keeps hangs finite & diagnosable)
#define MBAR_WAIT(mb, ph) do {                                                    \
    uint32_t _mb = (uint32_t)(mb); uint32_t _p = (uint32_t)(ph); uint32_t _d = 0; \
    for (int _i = 0; _i < (1 << 24); _i++) {                                      \
        asm volatile("{\n\t.reg .pred p;\n\t"                                     \
            "mbarrier.try_wait.parity.acquire.cta.shared::cta.b64 p, [%1], %2;\n\t" \
            "selp.b32 %0, 1, 0, p;\n\t}" : "=r"(_d) : "r"(_mb), "r"(_p) : "memory"); \
        if (_d) break;                                                            \
    }                                                                             \
} while (0)

#define TC_LD_X32(r, ta)                                                          \
    asm volatile("tcgen05.ld.sync.aligned.32x32b.x32.b32 "                        \
        "{%0,%1,%2,%3,%4,%5,%6,%7,%8,%9,%10,%11,%12,%13,%14,%15,"                 \
        "%16,%17,%18,%19,%20,%21,%22,%23,%24,%25,%26,%27,%28,%29,%30,%31}, [%32];"\
        : "=r"((r)[0]),"=r"((r)[1]),"=r"((r)[2]),"=r"((r)[3]),                    \
          "=r"((r)[4]),"=r"((r)[5]),"=r"((r)[6]),"=r"((r)[7]),                    \
          "=r"((r)[8]),"=r"((r)[9]),"=r"((r)[10]),"=r"((r)[11]),                  \
          "=r"((r)[12]),"=r"((r)[13]),"=r"((r)[14]),"=r"((r)[15]),                \
          "=r"((r)[16]),"=r"((r)[17]),"=r"((r)[18]),"=r"((r)[19]),                \
          "=r"((r)[20]),"=r"((r)[21]),"=r"((r)[22]),"=r"((r)[23]),                \
          "=r"((r)[24]),"=r"((r)[25]),"=r"((r)[26]),"=r"((r)[27]),                \
          "=r"((r)[28]),"=r"((r)[29]),"=r"((r)[30]),"=r"((r)[31])                 \
        : "r"(ta))

__device__ __forceinline__ void mma_ss_f16(uint32_t d, uint64_t ad, uint64_t bd,
                                           uint32_t idesc, uint32_t en) {
    asm volatile(
        "{\n\t.reg .pred p;\n\tsetp.ne.u32 p, %4, 0;\n\t"
        "tcgen05.mma.cta_group::1.kind::f16 [%0], %1, %2, %3, {%5,%5,%5,%5}, p;\n\t}"
        :: "r"(d), "l"(ad), "l"(bd), "r"(idesc), "r"(en), "r"(0u) : "memory");
}
#endif  // HAVE_TCGEN05

static constexpr uint64_t DESC_BASE_SW128 =
    (uint64_t(2) << 61) | (uint64_t(1) << 46) | (uint64_t(64) << 32) | (uint64_t(1) << 16);
#define MK_DESC(a) (DESC_BASE_SW128 | ((uint64_t)((a) >> 4) & 0x3FFF))
#define SWZ128(o)  ((o) ^ (((o) >> 3) & 0x70))

// ---------------- patchify + mask ----------------
__global__ void patchify_kernel(const float* __restrict__ x,
                                const float* __restrict__ mask) {
    int idx = blockIdx.x * 256 + threadIdx.x;
    if (idx >= MROWS * EMBED_IN) return;
    int row = idx / EMBED_IN;
    int e   = idx - row * EMBED_IN;
    int q   = e / 48;
    int d   = e - q * 48;
    int b   = row >> 2;
    int s   = row & 3;
    int n   = s * 64 + q;
    int pr  = n >> 4, pc = n & 15;
    int c   = d >> 4;
    int r   = d & 15;
    int i   = r >> 2, j = r & 3;
    float xv = x[((size_t)(b * 3 + c) * 64 + (pr * 4 + i)) * 64 + (pc * 4 + j)];
    float mv = mask[((size_t)b * 256 + n) * 48 + d];
    g_t[idx] = xv * mv;
}

// ---------------- activation fp32 -> bf16 hi/lo split (no transpose) ----------------
__global__ void convA_kernel(const float* __restrict__ src, __nv_bfloat16* __restrict__ dst,
                             int n) {
    int i = (blockIdx.x * 256 + threadIdx.x) * 4;
    if (i >= n) return;
    float4 v = *reinterpret_cast<const float4*>(src + i);
    __nv_bfloat16 h0 = __float2bfloat16(v.x), h1 = __float2bfloat16(v.y);
    __nv_bfloat16 h2 = __float2bfloat16(v.z), h3 = __float2bfloat16(v.w);
    __nv_bfloat162 hp0; hp0.x = h0; hp0.y = h1;
    __nv_bfloat162 hp1; hp1.x = h2; hp1.y = h3;
    __nv_bfloat162 lp0, lp1;
    lp0.x = __float2bfloat16(v.x - __bfloat162float(h0));
    lp0.y = __float2bfloat16(v.y - __bfloat162float(h1));
    lp1.x = __float2bfloat16(v.z - __bfloat162float(h2));
    lp1.y = __float2bfloat16(v.w - __bfloat162float(h3));
    *reinterpret_cast<__nv_bfloat162*>(dst + i)     = hp0;
    *reinterpret_cast<__nv_bfloat162*>(dst + i + 2) = hp1;
    *reinterpret_cast<__nv_bfloat162*>(dst + n + i)     = lp0;
    *reinterpret_cast<__nv_bfloat162*>(dst + n + i + 2) = lp1;
}

// ---------------- weight transpose + bf16 hi/lo split (vectorized) ----------------
// src: [K, Nsrc] fp32 ; dst: hi [Npad, K] bf16, lo follows at +Npad*K
__global__ void convT_kernel(const float* __restrict__ W, __nv_bfloat16* __restrict__ dst,
                             int K, int Npad, int Nsrc,
                             size_t srcStride, size_t dstStride) {
    int z = blockIdx.z;
    const float* src = W + (size_t)z * srcStride;
    __nv_bfloat16* hi = dst + (size_t)z * dstStride;
    __nv_bfloat16* lo = hi + (size_t)Npad * K;
    __shared__ float t[32][33];
    int k0 = blockIdx.y * 32, n0 = blockIdx.x * 32;
    int tid = threadIdx.x;
    // load 32x32: each thread 4 consecutive n
    {
        int k  = tid >> 3;
        int nq = (tid & 7) << 2;
        int n  = n0 + nq;
        if ((Nsrc & 3) == 0 && n + 3 < Nsrc) {
            float4 v = *reinterpret_cast<const float4*>(&src[(size_t)(k0 + k) * Nsrc + n]);
            t[k][nq] = v.x; t[k][nq+1] = v.y; t[k][nq+2] = v.z; t[k][nq+3] = v.w;
        } else {
            #pragma unroll
            for (int q = 0; q < 4; q++)
                t[k][nq+q] = (n + q < Nsrc) ? src[(size_t)(k0 + k) * Nsrc + n + q] : 0.f;
        }
    }
    __syncthreads();
    // store: 512 bf16x2 pairs per plane; each thread 2 pairs
    #pragma unroll
    for (int rep = 0; rep < 2; rep++) {
        int id = tid + rep * 256;          // (n:32) x (kp:16)
        int n  = id >> 4;
        int kp = id & 15;
        float v0 = t[kp * 2][n], v1 = t[kp * 2 + 1][n];
        __nv_bfloat16 h0 = __float2bfloat16(v0), h1 = __float2bfloat16(v1);
        __nv_bfloat162 hp; hp.x = h0; hp.y = h1;
        __nv_bfloat162 lp;
        lp.x = __float2bfloat16(v0 - __bfloat162float(h0));
        lp.y = __float2bfloat16(v1 - __bfloat162float(h1));
        size_t off = (size_t)(n0 + n) * K + k0 + kp * 2;
        *reinterpret_cast<__nv_bfloat162*>(hi + off) = hp;
        *reinterpret_cast<__nv_bfloat162*>(lo + off) = lp;
    }
}

// ---------------- layernorm ----------------
__global__ void ln_kernel(const float* __restrict__ h,
                          const float* __restrict__ gw,
                          const float* __restrict__ bw,
                          float* __restrict__ y) {
    int row = blockIdx.x;
    const float* xr = h + (size_t)row * HID;
    float s = 0.f, sq = 0.f;
    for (int c = threadIdx.x; c < HID; c += 256) {
        float v = xr[c];
        s += v;
        sq = fmaf(v, v, sq);
    }
    #pragma unroll
    for (int o = 16; o; o >>= 1) {
        s  += __shfl_xor_sync(0xffffffffu, s, o);
        sq += __shfl_xor_sync(0xffffffffu, sq, o);
    }
    __shared__ float ss[8], ssq[8];
    int w = threadIdx.x >> 5, l = threadIdx.x & 31;
    if (l == 0) { ss[w] = s; ssq[w] = sq; }
    __syncthreads();
    if (threadIdx.x == 0) {
        float a = 0.f, b2 = 0.f;
        #pragma unroll
        for (int i = 0; i < 8; i++) { a += ss[i]; b2 += ssq[i]; }
        ss[0] = a; ssq[0] = b2;
    }
    __syncthreads();
    float mean = ss[0] * (1.f / HID);
    float var  = ssq[0] * (1.f / HID) - mean * mean;
    float inv  = rsqrtf(var + 1e-5f);
    for (int c = threadIdx.x; c < HID; c += 256)
        y[(size_t)row * HID + c] = (xr[c] - mean) * inv * gw[c] + bw[c];
}

// ---------------- attention: per (batch, head); seq=4, dh=512 ----------------
__global__ void attn_kernel(const float* __restrict__ qkv, float* __restrict__ o) {
    int b  = blockIdx.x >> 2;
    int hd = blockIdx.x & 3;
    const float* base = qkv + (size_t)b * 4 * 6144 + hd * 512;
    int tid = threadIdx.x;

    float p[16];
    #pragma unroll
    for (int ij = 0; ij < 16; ij++) p[ij] = 0.f;
    for (int d = tid; d < 512; d += 128) {
        float qv[4], kv[4];
        #pragma unroll
        for (int s = 0; s < 4; s++) {
            qv[s] = base[s * 6144 + d];
            kv[s] = base[s * 6144 + 2048 + d];
        }
        #pragma unroll
        for (int i = 0; i < 4; i++)
            #pragma unroll
            for (int j = 0; j < 4; j++)
                p[i * 4 + j] = fmaf(qv[i], kv[j], p[i * 4 + j]);
    }
    #pragma unroll
    for (int ij = 0; ij < 16; ij++)
        #pragma unroll
        for (int off = 16; off; off >>= 1)
            p[ij] += __shfl_xor_sync(0xffffffffu, p[ij], off);

    __shared__ float dsh[4][16];
    __shared__ float probs[16];
    int w = tid >> 5, l = tid & 31;
    if (l == 0) {
        #pragma unroll
        for (int ij = 0; ij < 16; ij++) dsh[w][ij] = p[ij];
    }
    __syncthreads();
    if (tid < 4) {
        float row[4];
        #pragma unroll
        for (int j = 0; j < 4; j++)
            row[j] = (dsh[0][tid*4+j] + dsh[1][tid*4+j] + dsh[2][tid*4+j] + dsh[3][tid*4+j]) * ATTN_SCALE;
        float mx = fmaxf(fmaxf(row[0], row[1]), fmaxf(row[2], row[3]));
        float sum = 0.f;
        #pragma unroll
        for (int j = 0; j < 4; j++) { row[j] = expf(row[j] - mx); sum += row[j]; }
        float inv = 1.f / sum;
        #pragma unroll
        for (int j = 0; j < 4; j++) probs[tid * 4 + j] = row[j] * inv;
    }
    __syncthreads();
    for (int idx = tid; idx < 2048; idx += 128) {
        int i = idx >> 9, d = idx & 511;
        float acc = 0.f;
        #pragma unroll
        for (int j = 0; j < 4; j++)
            acc = fmaf(probs[i * 4 + j], base[j * 6144 + 4096 + d], acc);
        o[(size_t)(b * 4 + i) * 2048 + hd * 512 + d] = acc;
    }
}

// ---------------- double-buffered tcgen05 bf16-split GEMM ----------------
// C[M,N] = EPI(A @ W + bias); A pre-split hi/lo bf16 [M,K] (lo at +M*K),
// W pre-split hi/lo bf16 [Npad,K] (lo at +Npad*K)
// EPI: 0=none, 1=gelu(exact), 2=Cin+v, 3=2*Cin+v, 4=leaky(0.2)
#define TG_BM 128
#define TG_BN 128
#define TG_BK 64
#define TG_STAGE 65536
#define TG_SMEM (1024 + 2 * TG_STAGE)
#define TG_IDESC ((1u<<4)|(1u<<7)|(1u<<10)|((TG_BN/8)<<17)|((TG_BM/16)<<24))

template<int EPI>
__device__ __forceinline__ float apply_epi(float v, const float* __restrict__ Cin,
                                           int row, int col, int Nout) {
    if (EPI == 1)      v = 0.5f * v * (1.f + erff(v * 0.7071067811865475f));
    else if (EPI == 2) v = v + Cin[(size_t)row * Nout + col];
    else if (EPI == 3) v = v + 2.f * Cin[(size_t)row * Nout + col];
    else if (EPI == 4) v = (v > 0.f) ? v : 0.2f * v;
    return v;
}

#if HAVE_TCGEN05
// copy one 128x64 bf16 tile (16KB) from gmem (K-major, pitch K*2 bytes) into
// swizzled smem at byte offset smoff. 256 threads.
__device__ __forceinline__ void fill_tile(char* smem, int smoff, const char* base,
                                          size_t pitch, int tid) {
    #pragma unroll
    for (int it = 0; it < 4; it++) {
        int idx = it * 256 + tid;          // 1024 chunks of 16B
        int r   = idx >> 3;
        int b16 = (idx & 7) << 4;
        float4 v = *reinterpret_cast<const float4*>(base + (size_t)r * pitch + b16);
        *reinterpret_cast<float4*>(smem + smoff + SWZ128((uint32_t)(r * 128 + b16))) = v;
    }
}
#endif

template<int EPI>
__global__ void __launch_bounds__(256, 1)
tgemm(const __nv_bfloat16* __restrict__ Ahi, const __nv_bfloat16* __restrict__ Bhi,
      const float* __restrict__ bias, const float* __restrict__ Cin,
      float* __restrict__ Cout, int M, int Nout, int K, int Npad) {
    extern __shared__ char smem[];
    int tid = threadIdx.x;
    int row0 = blockIdx.y * TG_BM;
    int col0 = blockIdx.x * TG_BN;
    const char* Ah = (const char*)Ahi;
    const char* Al = (const char*)(Ahi + (size_t)M * K);
    const char* Bh = (const char*)Bhi;
    const char* Bl = (const char*)(Bhi + (size_t)Npad * K);
    size_t pitch = (size_t)K * 2;

#if HAVE_TCGEN05
    uint32_t sb = smem_u32(smem);
    int wid = tid >> 5, lid = tid & 31;
    const int SM_TM = 0, SM_MB0 = 8, SM_MB1 = 16;
    if (wid == 0) { TC_ALLOC(sb + SM_TM, 128); TC_RELINQ(); }
    if (tid == 0) { MBAR_INIT(sb + SM_MB0, 1); MBAR_INIT(sb + SM_MB1, 1); }
    __syncthreads();
    uint32_t tb;
    asm volatile("ld.shared.b32 %0, [%1];" : "=r"(tb) : "r"(sb + SM_TM));

    int niter = K / TG_BK;
    for (int ki = 0; ki < niter; ki++) {
        int s = ki & 1;
        uint32_t mb = sb + SM_MB0 + s * 8;
        int stg = 1024 + s * TG_STAGE;
        if (ki >= 2) { int c = (ki >> 1) - 1; MBAR_WAIT(mb, c & 1); }
        size_t koff = (size_t)(ki * TG_BK) * 2;
        fill_tile(smem, stg,         Ah + (size_t)row0 * pitch + koff, pitch, tid);
        fill_tile(smem, stg + 16384, Al + (size_t)row0 * pitch + koff, pitch, tid);
        fill_tile(smem, stg + 32768, Bh + (size_t)col0 * pitch + koff, pitch, tid);
        fill_tile(smem, stg + 49152, Bl + (size_t)col0 * pitch + koff, pitch, tid);
        FENCE_ASYNC();
        TC_FENCE_BEFORE();
        __syncthreads();
        if (wid == 0 && elect_one()) {
            TC_FENCE_AFTER();
            uint64_t adh = MK_DESC(sb + stg);
            uint64_t adl = MK_DESC(sb + stg + 16384);
            uint64_t bdh = MK_DESC(sb + stg + 32768);
            uint64_t bdl = MK_DESC(sb + stg + 49152);
            #pragma unroll
            for (int t = 0; t < 3; t++) {
                uint64_t ad = (t == 2) ? adl : adh;
                uint64_t bd = (t == 1) ? bdl : bdh;
                #pragma unroll
                for (int st = 0; st < 4; st++) {
                    uint32_t en = (ki > 0) || (t > 0) || (st > 0);
                    mma_ss_f16(tb, ad + st * 2, bd + st * 2, TG_IDESC, en);
                }
            }
            TC_COMMIT(mb);
        }
    }
    // wait for the final commit (tensor ops are in-order; last commit covers all)
    {
        int ki = niter - 1;
        uint32_t mb = sb + SM_MB0 + (ki & 1) * 8;
        MBAR_WAIT(mb, (ki >> 1) & 1);
    }
    TC_FENCE_AFTER();

    // epilogue: 8 warps; warp w -> subpartition w&3 (rows), column half w>>2
    {
        int sp = wid & 3, half = wid >> 2;
        int row = row0 + sp * 32 + lid;
        #pragma unroll
        for (int c2 = 0; c2 < 2; c2++) {
            int ch = half * 2 + c2;
            uint32_t r[32];
            TC_LD_X32(r, tb + ch * 32);
            TC_WAIT_LD();
            #pragma unroll
            for (int c = 0; c < 32; c++) {
                int col = col0 + ch * 32 + c;
                if (col >= Nout) continue;
                float v = __uint_as_float(r[c]) + bias[col];
                Cout[(size_t)row * Nout + col] = apply_epi<EPI>(v, Cin, row, col, Nout);
            }
        }
        TC_FENCE_BEFORE();
    }
    __syncthreads();
    if (tid == 0) { MBAR_INVAL(sb + SM_MB0); MBAR_INVAL(sb + SM_MB1); }
    __syncthreads();
    if (wid == 0) TC_DEALLOC(tb, 128);

#else  // ---------------- FFMA fallback (non-103a targets) ----------------
    int ty = tid >> 4, tx = tid & 15;
    float acc[8][8];
    #pragma unroll
    for (int i = 0; i < 8; i++)
        #pragma unroll
        for (int j = 0; j < 8; j++) acc[i][j] = 0.f;

    const int SM_AH = 1024, SM_AL = SM_AH + 16384;
    const int SM_BH = SM_AL + 16384, SM_BL = SM_BH + 16384;
    for (int k0 = 0; k0 < K; k0 += TG_BK) {
        for (int it = 0; it < 4; it++) {
            int idx = it * 256 + tid;
            int r   = idx >> 3;
            int b16 = (idx & 7) << 4;
            size_t go = (size_t)r * pitch + (size_t)k0 * 2 + b16;
            uint32_t off = SWZ128((uint32_t)(r * 128 + b16));
            *reinterpret_cast<float4*>(smem + SM_AH + off) = *reinterpret_cast<const float4*>(Ah + (size_t)row0 * pitch + go);
            *reinterpret_cast<float4*>(smem + SM_AL + off) = *reinterpret_cast<const float4*>(Al + (size_t)row0 * pitch + go);
            *reinterpret_cast<float4*>(smem + SM_BH + off) = *reinterpret_cast<const float4*>(Bh + (size_t)col0 * pitch + go);
            *reinterpret_cast<float4*>(smem + SM_BL + off) = *reinterpret_cast<const float4*>(Bl + (size_t)col0 * pitch + go);
        }
        __syncthreads();
        for (int kk = 0; kk < TG_BK; kk += 2) {
            float a0[8], a1[8], b0[8], b1[8];
            #pragma unroll
            for (int i = 0; i < 8; i++) {
                uint32_t off = SWZ128((uint32_t)((ty * 8 + i) * 128 + kk * 2));
                __nv_bfloat162 h = *reinterpret_cast<__nv_bfloat162*>(smem + SM_AH + off);
                __nv_bfloat162 l = *reinterpret_cast<__nv_bfloat162*>(smem + SM_AL + off);
                a0[i] = __bfloat162float(h.x) + __bfloat162float(l.x);
                a1[i] = __bfloat162float(h.y) + __bfloat162float(l.y);
            }
            #pragma unroll
            for (int j = 0; j < 8; j++) {
                uint32_t off = SWZ128((uint32_t)((tx * 8 + j) * 128 + kk * 2));
                __nv_bfloat162 h = *reinterpret_cast<__nv_bfloat162*>(smem + SM_BH + off);
                __nv_bfloat162 l = *reinterpret_cast<__nv_bfloat162*>(smem + SM_BL + off);
                b0[j] = __bfloat162float(h.x) + __bfloat162float(l.x);
                b1[j] = __bfloat162float(h.y) + __bfloat162float(l.y);
            }
            #pragma unroll
            for (int i = 0; i < 8; i++)
                #pragma unroll
                for (int j = 0; j < 8; j++) {
                    acc[i][j] = fmaf(a0[i], b0[j], acc[i][j]);
                    acc[i][j] = fmaf(a1[i], b1[j], acc[i][j]);
                }
        }
        __syncthreads();
    }
    #pragma unroll
    for (int i = 0; i < 8; i++) {
        int row = row0 + ty * 8 + i;
        #pragma unroll
        for (int j = 0; j < 8; j++) {
            int col = col0 + tx * 8 + j;
            if (col >= Nout) continue;
            float v = acc[i][j] + bias[col];
            Cout[(size_t)row * Nout + col] = apply_epi<EPI>(v, Cin, row, col, Nout);
        }
    }
#endif
}

// ---------------- host orchestration ----------------
extern "C" void kernel_launch(void* const* d_in, const int* in_sizes, int n_in,
                              void* d_out, int out_size) {
    const float* x       = (const float*)d_in[0];
    const float* mask    = (const float*)d_in[1];
    const float* embed_w = (const float*)d_in[2];
    const float* embed_b = (const float*)d_in[3];
    const float* ln_g    = (const float*)d_in[4];
    const float* ln_b    = (const float*)d_in[5];
    const float* mlp_w1  = (const float*)d_in[6];
    const float* mlp_b1  = (const float*)d_in[7];
    const float* mlp_w2  = (const float*)d_in[8];
    const float* mlp_b2  = (const float*)d_in[9];
    const float* qkv_w   = (const float*)d_in[10];
    const float* qkv_b   = (const float*)d_in[11];
    const float* out_w   = (const float*)d_in[12];
    const float* out_b   = (const float*)d_in[13];
    const float* fc1_w   = (const float*)d_in[14];
    const float* fc1_b   = (const float*)d_in[15];
    const float* fc2_w   = (const float*)d_in[16];
    const float* fc2_b   = (const float*)d_in[17];
    const float* fc3_w   = (const float*)d_in[18];
    const float* fc3_b   = (const float*)d_in[19];
    float* out = (float*)d_out;

    float *t, *h, *y, *z, *qkv, *o, *f1, *f2;
    cudaGetSymbolAddress((void**)&t,   g_t);
    cudaGetSymbolAddress((void**)&h,   g_h);
    cudaGetSymbolAddress((void**)&y,   g_y);
    cudaGetSymbolAddress((void**)&z,   g_z);
    cudaGetSymbolAddress((void**)&qkv, g_qkv);
    cudaGetSymbolAddress((void**)&o,   g_o);
    cudaGetSymbolAddress((void**)&f1,  g_f1);
    cudaGetSymbolAddress((void**)&f2,  g_f2);
    __nv_bfloat16 *act, *wE, *wM1, *wM2, *wQ, *wO, *wF1, *wF2, *wF3;
    cudaGetSymbolAddress((void**)&act, g_act);
    cudaGetSymbolAddress((void**)&wE,  g_embw);
    cudaGetSymbolAddress((void**)&wM1, g_m1w);
    cudaGetSymbolAddress((void**)&wM2, g_m2w);
    cudaGetSymbolAddress((void**)&wQ,  g_qkvw);
    cudaGetSymbolAddress((void**)&wO,  g_outw);
    cudaGetSymbolAddress((void**)&wF1, g_f1w);
    cudaGetSymbolAddress((void**)&wF2, g_f2w);
    cudaGetSymbolAddress((void**)&wF3, g_f3w);

    cudaFuncSetAttribute(tgemm<0>, cudaFuncAttributeMaxDynamicSharedMemorySize, TG_SMEM);
    cudaFuncSetAttribute(tgemm<1>, cudaFuncAttributeMaxDynamicSharedMemorySize, TG_SMEM);
    cudaFuncSetAttribute(tgemm<2>, cudaFuncAttributeMaxDynamicSharedMemorySize, TG_SMEM);
    cudaFuncSetAttribute(tgemm<3>, cudaFuncAttributeMaxDynamicSharedMemorySize, TG_SMEM);
    cudaFuncSetAttribute(tgemm<4>, cudaFuncAttributeMaxDynamicSharedMemorySize, TG_SMEM);

    dim3 cb(256);
    // weight conversions: src [K, Nsrc] -> hi/lo [Npad, K]
    convT_kernel<<<dim3(2048/32, 3072/32, 1), cb>>>(embed_w, wE, 3072, 2048, 2048, 0, 0);
    convT_kernel<<<dim3(4096/32, 2048/32, 4), cb>>>(mlp_w1, wM1, 2048, 4096, 4096,
                                                    (size_t)2048*4096, (size_t)2*4096*2048);
    convT_kernel<<<dim3(2048/32, 4096/32, 4), cb>>>(mlp_w2, wM2, 4096, 2048, 2048,
                                                    (size_t)4096*2048, (size_t)2*2048*4096);
    convT_kernel<<<dim3(6144/32, 2048/32, 4), cb>>>(qkv_w, wQ, 2048, 6144, 6144,
                                                    (size_t)2048*6144, (size_t)2*6144*2048);
    convT_kernel<<<dim3(2048/32, 2048/32, 4), cb>>>(out_w, wO, 2048, 2048, 2048,
                                                    (size_t)2048*2048, (size_t)2*2048*2048);
    convT_kernel<<<dim3(2048/32, 8192/32, 1), cb>>>(fc1_w, wF1, 8192, 2048, 2048, 0, 0);
    convT_kernel<<<dim3(2048/32, 2048/32, 1), cb>>>(fc2_w, wF2, 2048, 2048, 2048, 0, 0);
    convT_kernel<<<dim3(1024/32, 2048/32, 1), cb>>>(fc3_w, wF3, 2048, 1024, 1000, 0, 0);

    patchify_kernel<<<(MROWS * EMBED_IN + 255) / 256, 256>>>(x, mask);

    #define CONV_A(src, n) convA_kernel<<<(n)/1024, 256>>>(src, act, n)

    // 2) embed
    CONV_A(t, MROWS * EMBED_IN);
    tgemm<0><<<dim3(HID/128, MROWS/128), 256, TG_SMEM>>>(act, wE, embed_b, nullptr, h,
                                                         MROWS, HID, EMBED_IN, HID);

    // 3) MLP blocks
    for (int i = 0; i < 4; i++) {
        ln_kernel<<<MROWS, 256>>>(h, ln_g + (size_t)i * HID, ln_b + (size_t)i * HID, y);
        CONV_A(y, MROWS * HID);
        tgemm<1><<<dim3(2*HID/128, MROWS/128), 256, TG_SMEM>>>(
            act, wM1 + (size_t)i * 2 * 4096 * 2048, mlp_b1 + (size_t)i * 2 * HID,
            nullptr, z, MROWS, 2 * HID, HID, 2 * HID);
        CONV_A(z, MROWS * 2 * HID);
        tgemm<2><<<dim3(HID/128, MROWS/128), 256, TG_SMEM>>>(
            act, wM2 + (size_t)i * 2 * 2048 * 4096, mlp_b2 + (size_t)i * HID,
            h, h, MROWS, HID, 2 * HID, HID);
    }

    // 4) attention blocks (h_new = 2h + o@out_w + out_b)
    for (int i = 0; i < 4; i++) {
        CONV_A(h, MROWS * HID);
        tgemm<0><<<dim3(3*HID/128, MROWS/128), 256, TG_SMEM>>>(
            act, wQ + (size_t)i * 2 * 6144 * 2048, qkv_b + (size_t)i * 3 * HID,
            nullptr, qkv, MROWS, 3 * HID, HID, 3 * HID);
        attn_kernel<<<BATCH * 4, 128>>>(qkv, o);
        CONV_A(o, MROWS * HID);
        tgemm<3><<<dim3(HID/128, MROWS/128), 256, TG_SMEM>>>(
            act, wO + (size_t)i * 2 * 2048 * 2048, out_b + (size_t)i * HID,
            h, h, MROWS, HID, HID, HID);
    }

    // 5) final FCs; f = h viewed as (256, 8192)
    CONV_A(h, BATCH * SEQ * HID);
    tgemm<4><<<dim3(HID/128, BATCH/128), 256, TG_SMEM>>>(act, wF1, fc1_b, nullptr, f1,
                                                         BATCH, HID, SEQ * HID, HID);
    CONV_A(f1, BATCH * HID);
    tgemm<4><<<dim3(HID/128, BATCH/128), 256, TG_SMEM>>>(act, wF2, fc2_b, nullptr, f2,
                                                         BATCH, HID, HID, HID);
    CONV_A(f2, BATCH * HID);
    tgemm<0><<<dim3(1024/128, BATCH/128), 256, TG_SMEM>>>(act, wF3, fc3_b, nullptr, out,
                                                          BATCH, NCLASS, HID, 1024);
    #undef CONV_A
}